// round 15
// baseline (speedup 1.0000x reference)
#include <cuda_runtime.h>
#include <cuda_fp16.h>
#include <math.h>
#include <stdint.h>

typedef unsigned short u16;
typedef unsigned int   u32;

#define Bn 32
#define Sn 100
#define Tn 100
#define En 512
#define Hn 1024
#define Vn 32000
#define Gn 4096
#define NBLK 128
#define RED_F (16*1056)
#define PB_OFF 8192

// fp32 scratch
__device__ float g_XWenc[Bn*Sn*Gn];
__device__ float g_XWdec[Bn*Tn*Gn];
__device__ float g_h[Bn*Hn];
__device__ float g_c[Bn*Hn];
__device__ float g_hdf[Bn*Hn];
__device__ float g_scores[Bn*Sn];
__device__ float g_bias2[2048];          // [att1_b | zeros]

// fp16 operands
__device__ u16 g_hid16[Bn*Tn*Hn];
__device__ u16 g_eo16 [Bn*Sn*Hn];
__device__ u16 g_pe16 [(size_t)Bn*Sn*2048];   // [enc_proj | EP2] fp16 per row
__device__ u16 g_semb16[Bn*Sn*En];
__device__ u16 g_temb16[Bn*Tn*En];

// fragment-major fp16 state
__device__ uint4 g_ehf[2][4096];
__device__ uint4 g_dhf[2][4096];
__device__ uint4 g_fdf[2][4096];

// transposed [n][k] fp16 hi/lo weights
__device__ u16 w_ihE_h [(size_t)Gn*En],  w_ihE_l [(size_t)Gn*En];
__device__ u16 w_ihD0_h[(size_t)Gn*En],  w_ihD0_l[(size_t)Gn*En];
__device__ u16 w_pe_h  [(size_t)2048*Hn], w_pe_l [(size_t)2048*Hn];  // [att1 | cls1a]
__device__ u16 w_c2_h  [(size_t)Vn*Hn];

// fragment-major fp16 weights
__device__ uint4 w_hhE_f [512*64*32];
__device__ uint4 w_ihDH_f[512*64*32];
__device__ uint4 w_hhD_f [512*64*32];
__device__ uint4 w_c1b_f [128*64*32];

__device__ unsigned g_cnt, g_gen;
__device__ __forceinline__ void gbar() {
    __syncthreads();
    if (threadIdx.x == 0) {
        __threadfence();
        unsigned my = *((volatile unsigned*)&g_gen);
        unsigned a = atomicAdd(&g_cnt, 1u);
        if (a == NBLK - 1u) { g_cnt = 0u; __threadfence(); *((volatile unsigned*)&g_gen) = my + 1u; }
        else { while (*((volatile unsigned*)&g_gen) == my) {} }
        __threadfence();
    }
    __syncthreads();
}

__device__ __forceinline__ float sigm(float x){ return 1.0f/(1.0f + expf(-x)); }
__device__ __forceinline__ u16 fhi(float v){ return __half_as_ushort(__float2half_rn(v)); }
__device__ __forceinline__ u16 flo(float v){
    __half h = __float2half_rn(v);
    return __half_as_ushort(__float2half_rn(v - __half2float(h)));
}
__device__ __forceinline__ u32 pack2(u16 a, u16 b){ return (u32)a | ((u32)b << 16); }
__device__ __forceinline__ void mma16816h(float* c, const u32* a, u32 b0, u32 b1) {
    asm volatile("mma.sync.aligned.m16n8k16.row.col.f32.f16.f16.f32 "
        "{%0,%1,%2,%3},{%4,%5,%6,%7},{%8,%9},{%0,%1,%2,%3};"
        : "+f"(c[0]), "+f"(c[1]), "+f"(c[2]), "+f"(c[3])
        : "r"(a[0]), "r"(a[1]), "r"(a[2]), "r"(a[3]), "r"(b0), "r"(b1));
}
__device__ __forceinline__ void ldsm4(u32* r, u32 addr) {
    asm volatile("ldmatrix.sync.aligned.m8n8.x4.shared.b16 {%0,%1,%2,%3}, [%4];"
        : "=r"(r[0]), "=r"(r[1]), "=r"(r[2]), "=r"(r[3]) : "r"(addr));
}
__device__ __forceinline__ void frag_store16(u16* F, int row, int col, float v){
    int ch = col >> 4, kc = col & 15, mt = row >> 4, rg = row & 15;
    int lane = (rg & 7)*4 + ((kc >> 1) & 3);
    int w = ((kc >> 3) << 1) + (rg >> 3);
    size_t idx = ((size_t)(((ch*2 + mt)*32) + lane) << 3) + (w << 1) + (kc & 1);
    F[idx] = fhi(v);
}

// ---------- merged conversion / gather ----------
struct CJ { const float* W; void* Oh; void* Ol; int K, N, mode, boff; };
struct CJobs { CJ j[12]; };

__global__ void __launch_bounds__(256) conv_all(CJobs jb)
{
    __shared__ float tile[32][33];
    int blk = blockIdx.x, ji = 0;
    for (int i = 11; i >= 0; i--) if (blk >= jb.j[i].boff) { ji = i; break; }
    const CJ& J = jb.j[ji];
    int local = blk - J.boff;
    const int tid = threadIdx.x, lane = tid & 31;
    if (J.mode == 3 || J.mode == 4) {
        int ntl = J.N >> 5;
        int tk = local / ntl, tn = local % ntl;
        int n0 = tn*32, k0 = tk*32;
        int tx = lane, ty = tid >> 5;
        #pragma unroll
        for (int i = 0; i < 4; i++)
            tile[ty + i*8][tx] = J.W[(size_t)(k0 + ty + i*8)*J.N + n0 + tx];
        __syncthreads();
        u16* Oh = (u16*)J.Oh;
        if (J.mode == 3) {
            u16* Ol = (u16*)J.Ol;
            #pragma unroll
            for (int i = 0; i < 4; i++) {
                int nn = ty + i*8;
                float v = tile[tx][nn];
                Oh[(size_t)(n0+nn)*J.K + k0 + tx] = fhi(v);
                Ol[(size_t)(n0+nn)*J.K + k0 + tx] = flo(v);
            }
        } else {
            #pragma unroll
            for (int i = 0; i < 4; i++) {
                int nn = ty + i*8;
                Oh[(size_t)(n0+nn)*J.K + k0 + tx] = fhi(tile[tx][nn]);
            }
        }
    } else if (J.mode == 1) {
        int nch = J.K >> 4;
        int pair = local*8 + (tid >> 5);
        int ng = pair / nch, c = pair % nch;
        int n = ng*8 + (lane >> 2), k = c*16 + (lane & 3)*2;
        const float* W = J.W;
        float v0 = W[(size_t)k*J.N + n],     v1 = W[(size_t)(k+1)*J.N + n];
        float v2 = W[(size_t)(k+8)*J.N + n], v3 = W[(size_t)(k+9)*J.N + n];
        ((uint4*)J.Oh)[(size_t)pair*32 + lane] =
            make_uint4(pack2(fhi(v0),fhi(v1)), pack2(fhi(v2),fhi(v3)),
                       pack2(flo(v0),flo(v1)), pack2(flo(v2),flo(v3)));
    } else if (J.mode == 6) {
        float* O = (float*)J.Oh;
        for (int k = tid; k < 2048; k += 256)
            O[k] = (k < J.K) ? J.W[k] : 0.0f;
    } else {
        const int* idxp = (const int*)J.Ol;
        size_t base = (size_t)idxp[local] * J.K;
        u16* Oh = (u16*)J.Oh;
        for (int k = tid; k < J.K; k += 256)
            Oh[(size_t)local*J.K + k] = fhi(J.W[base + k]);
    }
}

// ---------- GEMM (2-term B): C = A(fp16) @ B(hi/lo)^T + bias ----------
__global__ void __launch_bounds__(256) gemm_h16(
    const u16* __restrict__ A,
    const u16* __restrict__ Bh, const u16* __restrict__ Bl,
    const float* __restrict__ bias, float* __restrict__ C, u16* __restrict__ C16,
    int N, int K)
{
    __shared__ __align__(16) u16 Ahs[2][128*24];
    __shared__ __align__(16) u16 Bhs[2][128*24], Bls[2][128*24];
    const int t = threadIdx.x, lane = t & 31, wid = t >> 5;
    const int wr = wid & 3, wc = wid >> 2;
    const int g = lane >> 2, tg = lane & 3;
    const int m0 = blockIdx.x * 128, n0 = blockIdx.y * 128;

    const int srow = t >> 1, sseg = (t & 1) * 8;
    const u16* Ap  = A  + (size_t)(m0 + srow) * K + sseg;
    const u16* Bph = Bh + (size_t)(n0 + srow) * K + sseg;
    const u16* Bpl = Bl + (size_t)(n0 + srow) * K + sseg;

    const int a_r = ((lane>>3)&1)*8 + (lane&7), a_c = (lane>>4)*8;
    const int b_r = (lane>>4)*8 + (lane&7),     b_c = ((lane>>3)&1)*8;
    u32 bAh[2], bBh[2], bBl[2];
    #pragma unroll
    for (int p = 0; p < 2; p++) {
        bAh[p] = (u32)__cvta_generic_to_shared(&Ahs[p][0]);
        bBh[p] = (u32)__cvta_generic_to_shared(&Bhs[p][0]);
        bBl[p] = (u32)__cvta_generic_to_shared(&Bls[p][0]);
    }

    float acc[2][8][4];
    #pragma unroll
    for (int i = 0; i < 2; i++)
        #pragma unroll
        for (int j = 0; j < 8; j++)
            #pragma unroll
            for (int q = 0; q < 4; q++) acc[i][j][q] = 0.0f;

    const int iters = K >> 4;
    uint4 aR = *(const uint4*)Ap;
    uint4 bhR = *(const uint4*)Bph, blR = *(const uint4*)Bpl;

    *(uint4*)&Ahs[0][srow*24 + sseg] = aR;
    *(uint4*)&Bhs[0][srow*24 + sseg] = bhR;
    *(uint4*)&Bls[0][srow*24 + sseg] = blR;
    __syncthreads();

    for (int kt = 0; kt < iters; kt++) {
        const int p = kt & 1;
        if (kt + 1 < iters) {
            aR  = *(const uint4*)(Ap + (kt+1)*16);
            bhR = *(const uint4*)(Bph + (kt+1)*16);
            blR = *(const uint4*)(Bpl + (kt+1)*16);
        }
        u32 ah[2][4];
        #pragma unroll
        for (int mt = 0; mt < 2; mt++) {
            u32 off = (u32)(((wr*32 + mt*16 + a_r)*24 + a_c) * 2);
            ldsm4(ah[mt], bAh[p] + off);
        }
        #pragma unroll
        for (int ntp = 0; ntp < 4; ntp++) {
            u32 off = (u32)(((wc*64 + ntp*16 + b_r)*24 + b_c) * 2);
            u32 bh4[4], bl4[4];
            ldsm4(bh4, bBh[p] + off);
            ldsm4(bl4, bBl[p] + off);
            #pragma unroll
            for (int e = 0; e < 2; e++) {
                int nt = ntp*2 + e;
                #pragma unroll
                for (int mt = 0; mt < 2; mt++) {
                    mma16816h(acc[mt][nt], ah[mt], bh4[e*2], bh4[e*2+1]);
                    mma16816h(acc[mt][nt], ah[mt], bl4[e*2], bl4[e*2+1]);
                }
            }
        }
        if (kt + 1 < iters) {
            const int q = p ^ 1;
            *(uint4*)&Ahs[q][srow*24 + sseg] = aR;
            *(uint4*)&Bhs[q][srow*24 + sseg] = bhR;
            *(uint4*)&Bls[q][srow*24 + sseg] = blR;
        }
        __syncthreads();
    }
    #pragma unroll
    for (int mt = 0; mt < 2; mt++)
        #pragma unroll
        for (int nt = 0; nt < 8; nt++) {
            int m = m0 + wr*32 + mt*16 + g;
            int n = n0 + wc*64 + nt*8 + tg*2;
            float b0v = bias[n], b1v = bias[n+1];
            float v00 = acc[mt][nt][0] + b0v, v01 = acc[mt][nt][1] + b1v;
            float v10 = acc[mt][nt][2] + b0v, v11 = acc[mt][nt][3] + b1v;
            if (C) {
                float* p2 = C + (size_t)m * N + n;
                *(float2*)p2 = make_float2(v00, v01);
                *(float2*)(p2 + (size_t)8*N) = make_float2(v10, v11);
            }
            if (C16) {
                u16* p3 = C16 + (size_t)m * N + n;
                *(u32*)p3 = pack2(fhi(v00), fhi(v01));
                *(u32*)(p3 + (size_t)8*N) = pack2(fhi(v10), fhi(v11));
            }
        }
}

// ---------- GEMM (single-term B): classifier ----------
__global__ void __launch_bounds__(256) gemm_h16s(
    const u16* __restrict__ A, const u16* __restrict__ Bh,
    const float* __restrict__ bias, float* __restrict__ C, int N, int K)
{
    __shared__ __align__(16) u16 Ahs[2][128*24];
    __shared__ __align__(16) u16 Bhs[2][128*24];
    const int t = threadIdx.x, lane = t & 31, wid = t >> 5;
    const int wr = wid & 3, wc = wid >> 2;
    const int g = lane >> 2, tg = lane & 3;
    const int m0 = blockIdx.x * 128, n0 = blockIdx.y * 128;

    const int srow = t >> 1, sseg = (t & 1) * 8;
    const u16* Ap  = A  + (size_t)(m0 + srow) * K + sseg;
    const u16* Bph = Bh + (size_t)(n0 + srow) * K + sseg;

    const int a_r = ((lane>>3)&1)*8 + (lane&7), a_c = (lane>>4)*8;
    const int b_r = (lane>>4)*8 + (lane&7),     b_c = ((lane>>3)&1)*8;
    u32 bAh[2], bBh[2];
    #pragma unroll
    for (int p = 0; p < 2; p++) {
        bAh[p] = (u32)__cvta_generic_to_shared(&Ahs[p][0]);
        bBh[p] = (u32)__cvta_generic_to_shared(&Bhs[p][0]);
    }

    float acc[2][8][4];
    #pragma unroll
    for (int i = 0; i < 2; i++)
        #pragma unroll
        for (int j = 0; j < 8; j++)
            #pragma unroll
            for (int q = 0; q < 4; q++) acc[i][j][q] = 0.0f;

    const int iters = K >> 4;
    uint4 aR = *(const uint4*)Ap;
    uint4 bhR = *(const uint4*)Bph;

    *(uint4*)&Ahs[0][srow*24 + sseg] = aR;
    *(uint4*)&Bhs[0][srow*24 + sseg] = bhR;
    __syncthreads();

    for (int kt = 0; kt < iters; kt++) {
        const int p = kt & 1;
        if (kt + 1 < iters) {
            aR  = *(const uint4*)(Ap + (kt+1)*16);
            bhR = *(const uint4*)(Bph + (kt+1)*16);
        }
        u32 ah[2][4];
        #pragma unroll
        for (int mt = 0; mt < 2; mt++) {
            u32 off = (u32)(((wr*32 + mt*16 + a_r)*24 + a_c) * 2);
            ldsm4(ah[mt], bAh[p] + off);
        }
        #pragma unroll
        for (int ntp = 0; ntp < 4; ntp++) {
            u32 off = (u32)(((wc*64 + ntp*16 + b_r)*24 + b_c) * 2);
            u32 bh4[4];
            ldsm4(bh4, bBh[p] + off);
            #pragma unroll
            for (int e = 0; e < 2; e++) {
                int nt = ntp*2 + e;
                #pragma unroll
                for (int mt = 0; mt < 2; mt++)
                    mma16816h(acc[mt][nt], ah[mt], bh4[e*2], bh4[e*2+1]);
            }
        }
        if (kt + 1 < iters) {
            const int q = p ^ 1;
            *(uint4*)&Ahs[q][srow*24 + sseg] = aR;
            *(uint4*)&Bhs[q][srow*24 + sseg] = bhR;
        }
        __syncthreads();
    }
    #pragma unroll
    for (int mt = 0; mt < 2; mt++)
        #pragma unroll
        for (int nt = 0; nt < 8; nt++) {
            int m = m0 + wr*32 + mt*16 + g;
            int n = n0 + wc*64 + nt*8 + tg*2;
            float b0v = bias[n], b1v = bias[n+1];
            float* p2 = C + (size_t)m * N + n;
            *(float2*)p2 = make_float2(acc[mt][nt][0] + b0v, acc[mt][nt][1] + b1v);
            *(float2*)(p2 + (size_t)8*N) = make_float2(acc[mt][nt][2] + b0v, acc[mt][nt][3] + b1v);
        }
}

// ---------- persistent encoder ----------
__global__ void __launch_bounds__(512) enc_persist()
{
    extern __shared__ float red_[];
    const int bk = blockIdx.x, tid = threadIdx.x, lane = tid & 31, wid = tid >> 5;
    const int g = lane >> 2, tg = lane & 3;

    { int i = bk*512 + tid;
      if (i < 16384) ((u32*)g_ehf[0])[i] = 0u; }
    float cst = 0.0f;
    gbar();

    for (int t = 0; t < Sn; t++) {
        const int rp = t & 1, wp2 = rp ^ 1;
        const uint4* Af = g_ehf[rp];

        float xg0, xg1, xg2, xg3;
        if (tid < 256) {
            const int bb = tid >> 3, jl = tid & 7;
            const size_t xw = ((size_t)(bb*Sn + t))*Gn + bk*8 + jl;
            xg0 = g_XWenc[xw]; xg1 = g_XWenc[xw+1024];
            xg2 = g_XWenc[xw+2048]; xg3 = g_XWenc[xw+3072];
        }

        float acc[2][4][4];
        #pragma unroll
        for (int a = 0; a < 2; a++)
            #pragma unroll
            for (int b = 0; b < 4; b++)
                #pragma unroll
                for (int q = 0; q < 4; q++) acc[a][b][q] = 0.0f;

        const int cb = wid*4;
        uint4 pf0 = Af[(cb*2)*32 + lane], pf1 = Af[(cb*2+1)*32 + lane];
        #pragma unroll
        for (int ks = 0; ks < 4; ks++) {
            const int c = cb + ks;
            uint4 f0 = pf0, f1 = pf1;
            if (ks < 3) {
                pf0 = Af[((c+1)*2)*32 + lane];
                pf1 = Af[((c+1)*2+1)*32 + lane];
            }
            #pragma unroll
            for (int nt = 0; nt < 4; nt++) {
                uint4 wq = w_hhE_f[((size_t)(nt*128 + bk)*64 + c)*32 + lane];
                mma16816h(acc[0][nt], (u32*)&f0, wq.x, wq.y);
                mma16816h(acc[0][nt], (u32*)&f0, wq.z, wq.w);
                mma16816h(acc[1][nt], (u32*)&f1, wq.x, wq.y);
                mma16816h(acc[1][nt], (u32*)&f1, wq.z, wq.w);
            }
        }
        float* rw0 = &red_[wid*1056];
        #pragma unroll
        for (int mt = 0; mt < 2; mt++)
            #pragma unroll
            for (int nt = 0; nt < 4; nt++) {
                int r0 = mt*16 + g, c0 = nt*8 + tg*2;
                rw0[r0*33 + c0]       = acc[mt][nt][0];
                rw0[r0*33 + c0 + 1]   = acc[mt][nt][1];
                rw0[(r0+8)*33 + c0]   = acc[mt][nt][2];
                rw0[(r0+8)*33 + c0+1] = acc[mt][nt][3];
            }
        __syncthreads();

        if (tid < 256) {
            const int bb = tid >> 3, jl = tid & 7, j = bk*8 + jl;
            float gi = xg0, gf = xg1, gg = xg2, go = xg3;
            #pragma unroll
            for (int w = 0; w < 16; w++) {
                const float* rw = &red_[w*1056 + bb*33];
                gi += rw[jl]; gf += rw[8+jl]; gg += rw[16+jl]; go += rw[24+jl];
            }
            cst = sigm(gf)*cst + sigm(gi)*tanhf(gg);
            float h = sigm(go)*tanhf(cst);
            g_eo16[((size_t)(bb*Sn + t))*Hn + j] = fhi(h);
            frag_store16((u16*)g_ehf[wp2], bb, j, h);
            if (t == Sn-1) { g_h[bb*Hn + j] = h; g_c[bb*Hn + j] = cst; }
        }
        gbar();
    }
}

// ---------- persistent decoder: 3 phases/step ----------
__global__ void __launch_bounds__(512) dec_persist(const float* __restrict__ cls1_b)
{
    extern __shared__ float red_[];
    const int bk = blockIdx.x, tid = threadIdx.x, lane = tid & 31, wid = tid >> 5;
    const int g = lane >> 2, tg = lane & 3;
    float* sc    = red_;
    float* wsm   = sc + 3200;
    float* stats = wsm + 3200;
    float* ctx   = stats + 64;

    { int i = bk*512 + tid;
      if (i < Bn*Hn) {
          float h0 = g_h[i];
          int row = i >> 10, col = i & 1023;
          frag_store16((u16*)g_dhf[0], row, col, h0);
          frag_store16((u16*)g_fdf[0], row, col, h0);
      } }
    float cst = (tid < 256) ? g_c[(tid>>3)*Hn + bk*8 + (tid&7)] : 0.0f;
    gbar();

    for (int t = 0; t < Tn; t++) {
        const int rp = t & 1, wp2 = rp ^ 1;

        // ---- P1: gates + LSTM cell ----
        {
            const uint4 *Af, *Wf;
            int cb;
            if (wid < 8) { Af = g_fdf[rp]; Wf = w_ihDH_f; cb = wid*8; }
            else         { Af = g_dhf[rp]; Wf = w_hhD_f;  cb = (wid-8)*8; }

            float xg0, xg1, xg2, xg3;
            if (tid < 256) {
                const int bb = tid >> 3, jl = tid & 7;
                const size_t xw = ((size_t)(bb*Tn + t))*Gn + bk*8 + jl;
                xg0 = g_XWdec[xw]; xg1 = g_XWdec[xw+1024];
                xg2 = g_XWdec[xw+2048]; xg3 = g_XWdec[xw+3072];
            }

            float acc[2][4][4];
            #pragma unroll
            for (int a = 0; a < 2; a++)
                #pragma unroll
                for (int b = 0; b < 4; b++)
                    #pragma unroll
                    for (int q = 0; q < 4; q++) acc[a][b][q] = 0.0f;

            uint4 pf0 = Af[(cb*2)*32 + lane], pf1 = Af[(cb*2+1)*32 + lane];
            #pragma unroll
            for (int ks = 0; ks < 8; ks++) {
                const int c = cb + ks;
                uint4 f0 = pf0, f1 = pf1;
                if (ks < 7) {
                    pf0 = Af[((c+1)*2)*32 + lane];
                    pf1 = Af[((c+1)*2+1)*32 + lane];
                }
                #pragma unroll
                for (int nt = 0; nt < 4; nt++) {
                    uint4 wq = Wf[((size_t)(nt*128 + bk)*64 + c)*32 + lane];
                    mma16816h(acc[0][nt], (u32*)&f0, wq.x, wq.y);
                    mma16816h(acc[0][nt], (u32*)&f0, wq.z, wq.w);
                    mma16816h(acc[1][nt], (u32*)&f1, wq.x, wq.y);
                    mma16816h(acc[1][nt], (u32*)&f1, wq.z, wq.w);
                }
            }
            float* rw0 = &red_[wid*1056];
            #pragma unroll
            for (int mt = 0; mt < 2; mt++)
                #pragma unroll
                for (int nt = 0; nt < 4; nt++) {
                    int r0 = mt*16 + g, c0 = nt*8 + tg*2;
                    rw0[r0*33 + c0]       = acc[mt][nt][0];
                    rw0[r0*33 + c0 + 1]   = acc[mt][nt][1];
                    rw0[(r0+8)*33 + c0]   = acc[mt][nt][2];
                    rw0[(r0+8)*33 + c0+1] = acc[mt][nt][3];
                }
            __syncthreads();
            if (tid < 256) {
                const int bb = tid >> 3, jl = tid & 7, j = bk*8 + jl;
                float gi = xg0, gf = xg1, gg = xg2, go = xg3;
                #pragma unroll
                for (int w = 0; w < 16; w++) {
                    const float* rw = &red_[w*1056 + bb*33];
                    gi += rw[jl]; gf += rw[8+jl]; gg += rw[16+jl]; go += rw[24+jl];
                }
                cst = sigm(gf)*cst + sigm(gi)*tanhf(gg);
                float h = sigm(go)*tanhf(cst);
                g_hdf[bb*Hn + j] = h;
                frag_store16((u16*)g_dhf[wp2], bb, j, h);
            }
        }
        gbar();

        // ---- P2: h@W1b partial MMA + attention scores (fp16 proj) ----
        {
            const uint4* Af = g_dhf[wp2];
            const int cb = wid*4;
            float fa[2][4];
            #pragma unroll
            for (int a = 0; a < 2; a++)
                #pragma unroll
                for (int q = 0; q < 4; q++) fa[a][q] = 0.0f;
            uint4 pf0 = Af[(cb*2)*32 + lane], pf1 = Af[(cb*2+1)*32 + lane];
            #pragma unroll
            for (int ks = 0; ks < 4; ks++) {
                const int c = cb + ks;
                uint4 f0 = pf0, f1 = pf1;
                if (ks < 3) {
                    pf0 = Af[((c+1)*2)*32 + lane];
                    pf1 = Af[((c+1)*2+1)*32 + lane];
                }
                uint4 wq = w_c1b_f[((size_t)bk*64 + c)*32 + lane];
                mma16816h(fa[0], (u32*)&f0, wq.x, wq.y);
                mma16816h(fa[0], (u32*)&f0, wq.z, wq.w);
                mma16816h(fa[1], (u32*)&f1, wq.x, wq.y);
                mma16816h(fa[1], (u32*)&f1, wq.z, wq.w);
            }
            float* pb = red_ + PB_OFF + wid*256;
            #pragma unroll
            for (int mt = 0; mt < 2; mt++) {
                int r0 = mt*16 + g;
                pb[r0*8 + tg*2]       = fa[mt][0];
                pb[r0*8 + tg*2 + 1]   = fa[mt][1];
                pb[(r0+8)*8 + tg*2]   = fa[mt][2];
                pb[(r0+8)*8 + tg*2+1] = fa[mt][3];
            }
            #pragma unroll
            for (int r = 0; r < 2; r++) {
                int pair = bk*16 + wid + r*2048;
                if (pair < Bn*Sn) {
                    int b = pair / Sn;
                    const uint4* ep4 = (const uint4*)(g_pe16 + (size_t)pair * 2048);
                    const float4* hv4 = (const float4*)(g_hdf + b * Hn);
                    float a = 0.f;
                    #pragma unroll
                    for (int it = 0; it < 4; it++) {
                        uint4 e = ep4[lane + 32*it];
                        float4 h0 = hv4[(lane + 32*it)*2];
                        float4 h1 = hv4[(lane + 32*it)*2 + 1];
                        float2 e0 = __half22float2(*(__half2*)&e.x);
                        float2 e1 = __half22float2(*(__half2*)&e.y);
                        float2 e2 = __half22float2(*(__half2*)&e.z);
                        float2 e3 = __half22float2(*(__half2*)&e.w);
                        a += e0.x*h0.x + e0.y*h0.y + e1.x*h0.z + e1.y*h0.w
                           + e2.x*h1.x + e2.y*h1.y + e3.x*h1.z + e3.y*h1.w;
                    }
                    #pragma unroll
                    for (int o = 16; o; o >>= 1) a += __shfl_xor_sync(0xffffffffu, a, o);
                    if (lane == 0) g_scores[pair] = a;
                }
            }
        }
        gbar();

        // ---- P3: softmax + context-over-EP2 + feed ----
        for (int i = tid; i < Bn*Sn; i += 512) sc[i] = g_scores[i];
        __syncthreads();
        #pragma unroll
        for (int q = 0; q < 2; q++) {
            int b = wid*2 + q;
            float m = -1e30f;
            for (int s = lane; s < Sn; s += 32) m = fmaxf(m, sc[b*Sn + s]);
            #pragma unroll
            for (int o = 16; o; o >>= 1) m = fmaxf(m, __shfl_xor_sync(0xffffffffu, m, o));
            float su = 0.f;
            for (int s = lane; s < Sn; s += 32) su += expf(sc[b*Sn + s] - m);
            #pragma unroll
            for (int o = 16; o; o >>= 1) su += __shfl_xor_sync(0xffffffffu, su, o);
            if (lane == 0) { stats[b] = m; stats[32 + b] = 1.0f / su; }
        }
        __syncthreads();
        for (int i = tid; i < Bn*Sn; i += 512) {
            int b = i / Sn;
            wsm[i] = expf(sc[i] - stats[b]) * stats[32 + b];
        }
        __syncthreads();
        {
            const int half = tid >> 8, ct = tid & 255;
            const int bb = ct >> 3, jl = ct & 7, j = bk*8 + jl;
            const __half* e2 = (const __half*)(g_pe16
                + ((size_t)(bb*Sn + half*50))*2048 + 1024 + j);
            const float* wv = wsm + bb*Sn + half*50;
            float a = 0.f;
            #pragma unroll 10
            for (int s = 0; s < 50; s++) a += wv[s] * __half2float(e2[(size_t)s * 2048]);
            ctx[tid] = a;
        }
        __syncthreads();
        if (tid < 256) {
            const int bb = tid >> 3, jl = tid & 7, j = bk*8 + jl;
            float a = ctx[tid] + ctx[256 + tid] + cls1_b[j];
            #pragma unroll
            for (int w = 0; w < 16; w++) a += red_[PB_OFF + w*256 + bb*8 + jl];
            float f = tanhf(a);
            frag_store16((u16*)g_fdf[wp2], bb, j, f);
            g_hid16[((size_t)(bb*Tn + t))*Hn + j] = fhi(f);
        }
        gbar();
    }
}

extern "C" void kernel_launch(void* const* d_in, const int* in_sizes, int n_in,
                              void* d_out, int out_size)
{
    const int*   source_data = (const int*)  d_in[0];
    const int*   target_data = (const int*)  d_in[1];
    const float* src_emb  = (const float*)d_in[2];
    const float* tgt_emb  = (const float*)d_in[3];
    const float* enc_Wih  = (const float*)d_in[4];
    const float* enc_Whh  = (const float*)d_in[5];
    const float* enc_b    = (const float*)d_in[6];
    const float* dec_Wih  = (const float*)d_in[7];
    const float* dec_Whh  = (const float*)d_in[8];
    const float* dec_b    = (const float*)d_in[9];
    const float* att1_W   = (const float*)d_in[10];
    const float* att1_b   = (const float*)d_in[11];
    const float* cls1_W   = (const float*)d_in[12];
    const float* cls1_b   = (const float*)d_in[13];
    const float* cls2_W   = (const float*)d_in[14];
    const float* cls2_b   = (const float*)d_in[15];
    float* out = (float*)d_out;

    float *XWenc, *XWdec, *bias2;
    void *ihE_h,*ihE_l,*ihD0_h,*ihD0_l,*pe_h,*pe_l,*c2_h;
    void *hhE_f,*ihDH_f,*hhD_f,*c1b_f;
    void *hid16,*eo16,*pe16,*semb16,*temb16;
    cudaGetSymbolAddress((void**)&XWenc,  g_XWenc);
    cudaGetSymbolAddress((void**)&XWdec,  g_XWdec);
    cudaGetSymbolAddress((void**)&bias2,  g_bias2);
    cudaGetSymbolAddress(&hid16,  g_hid16);  cudaGetSymbolAddress(&eo16, g_eo16);
    cudaGetSymbolAddress(&pe16,   g_pe16);
    cudaGetSymbolAddress(&semb16, g_semb16); cudaGetSymbolAddress(&temb16, g_temb16);
    cudaGetSymbolAddress(&ihE_h,  w_ihE_h);  cudaGetSymbolAddress(&ihE_l,  w_ihE_l);
    cudaGetSymbolAddress(&ihD0_h, w_ihD0_h); cudaGetSymbolAddress(&ihD0_l, w_ihD0_l);
    cudaGetSymbolAddress(&pe_h,   w_pe_h);   cudaGetSymbolAddress(&pe_l,   w_pe_l);
    cudaGetSymbolAddress(&c2_h,   w_c2_h);
    cudaGetSymbolAddress(&hhE_f,  w_hhE_f);  cudaGetSymbolAddress(&ihDH_f, w_ihDH_f);
    cudaGetSymbolAddress(&hhD_f,  w_hhD_f);  cudaGetSymbolAddress(&c1b_f,  w_c1b_f);

    cudaFuncSetAttribute(enc_persist, cudaFuncAttributeMaxDynamicSharedMemorySize, RED_F*4);
    cudaFuncSetAttribute(dec_persist, cudaFuncAttributeMaxDynamicSharedMemorySize, RED_F*4);

    CJobs jb;
    jb.j[0]  = { enc_Wih,                     ihE_h,  ihE_l,   512, 4096, 3, 0     };
    jb.j[1]  = { dec_Wih,                     ihD0_h, ihD0_l,  512, 4096, 3, 2048  };
    jb.j[2]  = { att1_W,                      pe_h,   pe_l,   1024, 1024, 3, 4096  };
    jb.j[3]  = { cls2_W,                      c2_h,   nullptr,1024, Vn,   4, 5120  };
    jb.j[4]  = { cls1_W,  (u16*)pe_h + (size_t)1024*1024,
                          (u16*)pe_l + (size_t)1024*1024,     1024, 1024, 3, 37120 };
    jb.j[5]  = { enc_Whh,                     hhE_f,  nullptr,1024, 4096, 1, 38144 };
    jb.j[6]  = { dec_Wih + (size_t)512*4096,  ihDH_f, nullptr,1024, 4096, 1, 42240 };
    jb.j[7]  = { dec_Whh,                     hhD_f,  nullptr,1024, 4096, 1, 46336 };
    jb.j[8]  = { cls1_W + (size_t)1024*1024,  c1b_f,  nullptr,1024, 1024, 1, 50432 };
    jb.j[9]  = { src_emb, semb16, (void*)source_data,  512, 0, 5, 51456 };
    jb.j[10] = { tgt_emb, temb16, (void*)target_data,  512, 0, 5, 54656 };
    jb.j[11] = { att1_b,  bias2,  nullptr,            1024, 0, 6, 57856 };
    conv_all<<<57857, 256>>>(jb);                                              // 1

    gemm_h16<<<dim3(25, 32), 256>>>((u16*)semb16,
        (u16*)ihE_h, (u16*)ihE_l, enc_b, XWenc, nullptr, Gn, En);              // 2
    gemm_h16<<<dim3(25, 32), 256>>>((u16*)temb16,
        (u16*)ihD0_h, (u16*)ihD0_l, dec_b, XWdec, nullptr, Gn, En);            // 3
    enc_persist<<<NBLK, 512, RED_F*4>>>();                                     // 4
    gemm_h16<<<dim3(25, 16), 256>>>((u16*)eo16,
        (u16*)pe_h, (u16*)pe_l, bias2, nullptr, (u16*)pe16, 2048, Hn);         // 5
    dec_persist<<<NBLK, 512, RED_F*4>>>(cls1_b);                               // 6  <- ncu
    gemm_h16s<<<dim3(25, 250), 256>>>((u16*)hid16,
        (u16*)c2_h, cls2_b, out, Vn, Hn);                                      // 7
}

// round 16
// speedup vs baseline: 1.0645x; 1.0645x over previous
#include <cuda_runtime.h>
#include <cuda_fp16.h>
#include <math.h>
#include <stdint.h>

typedef unsigned short u16;
typedef unsigned int   u32;

#define Bn 32
#define Sn 100
#define Tn 100
#define En 512
#define Hn 1024
#define Vn 32000
#define Gn 4096
#define NBLK 128
#define RED_F (16*1056)
#define PB_OFF 8192

// fp32 scratch
__device__ float g_XWenc[Bn*Sn*Gn];
__device__ float g_XWdec[Bn*Tn*Gn];
__device__ float g_h[Bn*Hn];
__device__ float g_c[Bn*Hn];
__device__ float g_hdf[Bn*Hn];
__device__ float g_scores[Bn*Sn];
__device__ float g_bias2[2048];          // [att1_b | zeros]

// fp16 operands
__device__ u16 g_hid16[Bn*Tn*Hn];
__device__ u16 g_eo16 [Bn*Sn*Hn];
__device__ u16 g_pe16 [(size_t)Bn*Sn*2048];   // [enc_proj | EP2] fp16 per row
__device__ u16 g_semb16[Bn*Sn*En];
__device__ u16 g_temb16[Bn*Tn*En];

// fragment-major fp16 state
__device__ uint4 g_ehf[2][4096];
__device__ uint4 g_dhf[2][4096];
__device__ uint4 g_fdf[2][4096];

// transposed [n][k] fp16 weights (feed-forward GEMMs)
__device__ u16 w_ihE_h [(size_t)Gn*En],  w_ihE_l [(size_t)Gn*En];
__device__ u16 w_ihD0_h[(size_t)Gn*En],  w_ihD0_l[(size_t)Gn*En];
__device__ u16 w_pe_h  [(size_t)2048*Hn], w_pe_l [(size_t)2048*Hn];  // [att1 | cls1a]
__device__ u16 w_c2_h  [(size_t)Vn*Hn];

// fragment-major fp16 weights, HI only: uint4 = {c0.b0, c0.b1, c1.b0, c1.b1}
// idx = (ng*nch2 + c2)*32 + lane,  c2 = k32-chunk
__device__ uint4 w_hhE_f [512*32*32];
__device__ uint4 w_ihDH_f[512*32*32];
__device__ uint4 w_hhD_f [512*32*32];
__device__ uint4 w_c1b_f [128*32*32];

__device__ unsigned g_cnt, g_gen;
__device__ __forceinline__ void gbar() {
    __syncthreads();
    if (threadIdx.x == 0) {
        __threadfence();
        unsigned my = *((volatile unsigned*)&g_gen);
        unsigned a = atomicAdd(&g_cnt, 1u);
        if (a == NBLK - 1u) { g_cnt = 0u; __threadfence(); *((volatile unsigned*)&g_gen) = my + 1u; }
        else { while (*((volatile unsigned*)&g_gen) == my) {} }
        __threadfence();
    }
    __syncthreads();
}

__device__ __forceinline__ float sigm(float x){ return 1.0f/(1.0f + expf(-x)); }
__device__ __forceinline__ u16 fhi(float v){ return __half_as_ushort(__float2half_rn(v)); }
__device__ __forceinline__ u16 flo(float v){
    __half h = __float2half_rn(v);
    return __half_as_ushort(__float2half_rn(v - __half2float(h)));
}
__device__ __forceinline__ u32 pack2(u16 a, u16 b){ return (u32)a | ((u32)b << 16); }
__device__ __forceinline__ void mma16816h(float* c, const u32* a, u32 b0, u32 b1) {
    asm volatile("mma.sync.aligned.m16n8k16.row.col.f32.f16.f16.f32 "
        "{%0,%1,%2,%3},{%4,%5,%6,%7},{%8,%9},{%0,%1,%2,%3};"
        : "+f"(c[0]), "+f"(c[1]), "+f"(c[2]), "+f"(c[3])
        : "r"(a[0]), "r"(a[1]), "r"(a[2]), "r"(a[3]), "r"(b0), "r"(b1));
}
__device__ __forceinline__ void ldsm4(u32* r, u32 addr) {
    asm volatile("ldmatrix.sync.aligned.m8n8.x4.shared.b16 {%0,%1,%2,%3}, [%4];"
        : "=r"(r[0]), "=r"(r[1]), "=r"(r[2]), "=r"(r[3]) : "r"(addr));
}
__device__ __forceinline__ void frag_store16(u16* F, int row, int col, float v){
    int ch = col >> 4, kc = col & 15, mt = row >> 4, rg = row & 15;
    int lane = (rg & 7)*4 + ((kc >> 1) & 3);
    int w = ((kc >> 3) << 1) + (rg >> 3);
    size_t idx = ((size_t)(((ch*2 + mt)*32) + lane) << 3) + (w << 1) + (kc & 1);
    F[idx] = fhi(v);
}

// ---------- merged conversion / gather ----------
struct CJ { const float* W; void* Oh; void* Ol; int K, N, mode, boff; };
struct CJobs { CJ j[12]; };

__global__ void __launch_bounds__(256) conv_all(CJobs jb)
{
    __shared__ float tile[32][33];
    int blk = blockIdx.x, ji = 0;
    for (int i = 11; i >= 0; i--) if (blk >= jb.j[i].boff) { ji = i; break; }
    const CJ& J = jb.j[ji];
    int local = blk - J.boff;
    const int tid = threadIdx.x, lane = tid & 31;
    if (J.mode == 3 || J.mode == 4) {
        int ntl = J.N >> 5;
        int tk = local / ntl, tn = local % ntl;
        int n0 = tn*32, k0 = tk*32;
        int tx = lane, ty = tid >> 5;
        #pragma unroll
        for (int i = 0; i < 4; i++)
            tile[ty + i*8][tx] = J.W[(size_t)(k0 + ty + i*8)*J.N + n0 + tx];
        __syncthreads();
        u16* Oh = (u16*)J.Oh;
        if (J.mode == 3) {
            u16* Ol = (u16*)J.Ol;
            #pragma unroll
            for (int i = 0; i < 4; i++) {
                int nn = ty + i*8;
                float v = tile[tx][nn];
                Oh[(size_t)(n0+nn)*J.K + k0 + tx] = fhi(v);
                Ol[(size_t)(n0+nn)*J.K + k0 + tx] = flo(v);
            }
        } else {
            #pragma unroll
            for (int i = 0; i < 4; i++) {
                int nn = ty + i*8;
                Oh[(size_t)(n0+nn)*J.K + k0 + tx] = fhi(tile[tx][nn]);
            }
        }
    } else if (J.mode == 1) {
        // fragment-major fp16 HI only, two k16 chunks per uint4
        int nch2 = J.K >> 5;
        int pair = local*8 + (tid >> 5);
        int ng = pair / nch2, c2 = pair % nch2;
        int n = ng*8 + (lane >> 2), k = c2*32 + (lane & 3)*2;
        const float* W = J.W;
        float v0 = W[(size_t)k*J.N + n],      v1 = W[(size_t)(k+1)*J.N + n];
        float v2 = W[(size_t)(k+8)*J.N + n],  v3 = W[(size_t)(k+9)*J.N + n];
        float v4 = W[(size_t)(k+16)*J.N + n], v5 = W[(size_t)(k+17)*J.N + n];
        float v6 = W[(size_t)(k+24)*J.N + n], v7 = W[(size_t)(k+25)*J.N + n];
        ((uint4*)J.Oh)[(size_t)pair*32 + lane] =
            make_uint4(pack2(fhi(v0),fhi(v1)), pack2(fhi(v2),fhi(v3)),
                       pack2(fhi(v4),fhi(v5)), pack2(fhi(v6),fhi(v7)));
    } else if (J.mode == 6) {
        float* O = (float*)J.Oh;
        for (int k = tid; k < 2048; k += 256)
            O[k] = (k < J.K) ? J.W[k] : 0.0f;
    } else {
        const int* idxp = (const int*)J.Ol;
        size_t base = (size_t)idxp[local] * J.K;
        u16* Oh = (u16*)J.Oh;
        for (int k = tid; k < J.K; k += 256)
            Oh[(size_t)local*J.K + k] = fhi(J.W[base + k]);
    }
}

// ---------- GEMM (2-term B): C = A(fp16) @ B(hi/lo)^T + bias ----------
__global__ void __launch_bounds__(256) gemm_h16(
    const u16* __restrict__ A,
    const u16* __restrict__ Bh, const u16* __restrict__ Bl,
    const float* __restrict__ bias, float* __restrict__ C, u16* __restrict__ C16,
    int N, int K)
{
    __shared__ __align__(16) u16 Ahs[2][128*24];
    __shared__ __align__(16) u16 Bhs[2][128*24], Bls[2][128*24];
    const int t = threadIdx.x, lane = t & 31, wid = t >> 5;
    const int wr = wid & 3, wc = wid >> 2;
    const int g = lane >> 2, tg = lane & 3;
    const int m0 = blockIdx.x * 128, n0 = blockIdx.y * 128;

    const int srow = t >> 1, sseg = (t & 1) * 8;
    const u16* Ap  = A  + (size_t)(m0 + srow) * K + sseg;
    const u16* Bph = Bh + (size_t)(n0 + srow) * K + sseg;
    const u16* Bpl = Bl + (size_t)(n0 + srow) * K + sseg;

    const int a_r = ((lane>>3)&1)*8 + (lane&7), a_c = (lane>>4)*8;
    const int b_r = (lane>>4)*8 + (lane&7),     b_c = ((lane>>3)&1)*8;
    u32 bAh[2], bBh[2], bBl[2];
    #pragma unroll
    for (int p = 0; p < 2; p++) {
        bAh[p] = (u32)__cvta_generic_to_shared(&Ahs[p][0]);
        bBh[p] = (u32)__cvta_generic_to_shared(&Bhs[p][0]);
        bBl[p] = (u32)__cvta_generic_to_shared(&Bls[p][0]);
    }

    float acc[2][8][4];
    #pragma unroll
    for (int i = 0; i < 2; i++)
        #pragma unroll
        for (int j = 0; j < 8; j++)
            #pragma unroll
            for (int q = 0; q < 4; q++) acc[i][j][q] = 0.0f;

    const int iters = K >> 4;
    uint4 aR = *(const uint4*)Ap;
    uint4 bhR = *(const uint4*)Bph, blR = *(const uint4*)Bpl;

    *(uint4*)&Ahs[0][srow*24 + sseg] = aR;
    *(uint4*)&Bhs[0][srow*24 + sseg] = bhR;
    *(uint4*)&Bls[0][srow*24 + sseg] = blR;
    __syncthreads();

    for (int kt = 0; kt < iters; kt++) {
        const int p = kt & 1;
        if (kt + 1 < iters) {
            aR  = *(const uint4*)(Ap + (kt+1)*16);
            bhR = *(const uint4*)(Bph + (kt+1)*16);
            blR = *(const uint4*)(Bpl + (kt+1)*16);
        }
        u32 ah[2][4];
        #pragma unroll
        for (int mt = 0; mt < 2; mt++) {
            u32 off = (u32)(((wr*32 + mt*16 + a_r)*24 + a_c) * 2);
            ldsm4(ah[mt], bAh[p] + off);
        }
        #pragma unroll
        for (int ntp = 0; ntp < 4; ntp++) {
            u32 off = (u32)(((wc*64 + ntp*16 + b_r)*24 + b_c) * 2);
            u32 bh4[4], bl4[4];
            ldsm4(bh4, bBh[p] + off);
            ldsm4(bl4, bBl[p] + off);
            #pragma unroll
            for (int e = 0; e < 2; e++) {
                int nt = ntp*2 + e;
                #pragma unroll
                for (int mt = 0; mt < 2; mt++) {
                    mma16816h(acc[mt][nt], ah[mt], bh4[e*2], bh4[e*2+1]);
                    mma16816h(acc[mt][nt], ah[mt], bl4[e*2], bl4[e*2+1]);
                }
            }
        }
        if (kt + 1 < iters) {
            const int q = p ^ 1;
            *(uint4*)&Ahs[q][srow*24 + sseg] = aR;
            *(uint4*)&Bhs[q][srow*24 + sseg] = bhR;
            *(uint4*)&Bls[q][srow*24 + sseg] = blR;
        }
        __syncthreads();
    }
    #pragma unroll
    for (int mt = 0; mt < 2; mt++)
        #pragma unroll
        for (int nt = 0; nt < 8; nt++) {
            int m = m0 + wr*32 + mt*16 + g;
            int n = n0 + wc*64 + nt*8 + tg*2;
            float b0v = bias[n], b1v = bias[n+1];
            float v00 = acc[mt][nt][0] + b0v, v01 = acc[mt][nt][1] + b1v;
            float v10 = acc[mt][nt][2] + b0v, v11 = acc[mt][nt][3] + b1v;
            if (C) {
                float* p2 = C + (size_t)m * N + n;
                *(float2*)p2 = make_float2(v00, v01);
                *(float2*)(p2 + (size_t)8*N) = make_float2(v10, v11);
            }
            if (C16) {
                u16* p3 = C16 + (size_t)m * N + n;
                *(u32*)p3 = pack2(fhi(v00), fhi(v01));
                *(u32*)(p3 + (size_t)8*N) = pack2(fhi(v10), fhi(v11));
            }
        }
}

// ---------- GEMM (single-term B): classifier ----------
__global__ void __launch_bounds__(256) gemm_h16s(
    const u16* __restrict__ A, const u16* __restrict__ Bh,
    const float* __restrict__ bias, float* __restrict__ C, int N, int K)
{
    __shared__ __align__(16) u16 Ahs[2][128*24];
    __shared__ __align__(16) u16 Bhs[2][128*24];
    const int t = threadIdx.x, lane = t & 31, wid = t >> 5;
    const int wr = wid & 3, wc = wid >> 2;
    const int g = lane >> 2, tg = lane & 3;
    const int m0 = blockIdx.x * 128, n0 = blockIdx.y * 128;

    const int srow = t >> 1, sseg = (t & 1) * 8;
    const u16* Ap  = A  + (size_t)(m0 + srow) * K + sseg;
    const u16* Bph = Bh + (size_t)(n0 + srow) * K + sseg;

    const int a_r = ((lane>>3)&1)*8 + (lane&7), a_c = (lane>>4)*8;
    const int b_r = (lane>>4)*8 + (lane&7),     b_c = ((lane>>3)&1)*8;
    u32 bAh[2], bBh[2];
    #pragma unroll
    for (int p = 0; p < 2; p++) {
        bAh[p] = (u32)__cvta_generic_to_shared(&Ahs[p][0]);
        bBh[p] = (u32)__cvta_generic_to_shared(&Bhs[p][0]);
    }

    float acc[2][8][4];
    #pragma unroll
    for (int i = 0; i < 2; i++)
        #pragma unroll
        for (int j = 0; j < 8; j++)
            #pragma unroll
            for (int q = 0; q < 4; q++) acc[i][j][q] = 0.0f;

    const int iters = K >> 4;
    uint4 aR = *(const uint4*)Ap;
    uint4 bhR = *(const uint4*)Bph;

    *(uint4*)&Ahs[0][srow*24 + sseg] = aR;
    *(uint4*)&Bhs[0][srow*24 + sseg] = bhR;
    __syncthreads();

    for (int kt = 0; kt < iters; kt++) {
        const int p = kt & 1;
        if (kt + 1 < iters) {
            aR  = *(const uint4*)(Ap + (kt+1)*16);
            bhR = *(const uint4*)(Bph + (kt+1)*16);
        }
        u32 ah[2][4];
        #pragma unroll
        for (int mt = 0; mt < 2; mt++) {
            u32 off = (u32)(((wr*32 + mt*16 + a_r)*24 + a_c) * 2);
            ldsm4(ah[mt], bAh[p] + off);
        }
        #pragma unroll
        for (int ntp = 0; ntp < 4; ntp++) {
            u32 off = (u32)(((wc*64 + ntp*16 + b_r)*24 + b_c) * 2);
            u32 bh4[4];
            ldsm4(bh4, bBh[p] + off);
            #pragma unroll
            for (int e = 0; e < 2; e++) {
                int nt = ntp*2 + e;
                #pragma unroll
                for (int mt = 0; mt < 2; mt++)
                    mma16816h(acc[mt][nt], ah[mt], bh4[e*2], bh4[e*2+1]);
            }
        }
        if (kt + 1 < iters) {
            const int q = p ^ 1;
            *(uint4*)&Ahs[q][srow*24 + sseg] = aR;
            *(uint4*)&Bhs[q][srow*24 + sseg] = bhR;
        }
        __syncthreads();
    }
    #pragma unroll
    for (int mt = 0; mt < 2; mt++)
        #pragma unroll
        for (int nt = 0; nt < 8; nt++) {
            int m = m0 + wr*32 + mt*16 + g;
            int n = n0 + wc*64 + nt*8 + tg*2;
            float b0v = bias[n], b1v = bias[n+1];
            float* p2 = C + (size_t)m * N + n;
            *(float2*)p2 = make_float2(acc[mt][nt][0] + b0v, acc[mt][nt][1] + b1v);
            *(float2*)(p2 + (size_t)8*N) = make_float2(acc[mt][nt][2] + b0v, acc[mt][nt][3] + b1v);
        }
}

// ---------- persistent encoder ----------
__global__ void __launch_bounds__(512) enc_persist()
{
    extern __shared__ float red_[];
    const int bk = blockIdx.x, tid = threadIdx.x, lane = tid & 31, wid = tid >> 5;
    const int g = lane >> 2, tg = lane & 3;

    { int i = bk*512 + tid;
      if (i < 16384) ((u32*)g_ehf[0])[i] = 0u; }
    float cst = 0.0f;
    gbar();

    for (int t = 0; t < Sn; t++) {
        const int rp = t & 1, wp2 = rp ^ 1;
        const uint4* Af = g_ehf[rp];

        float xg0, xg1, xg2, xg3;
        if (tid < 256) {
            const int bb = tid >> 3, jl = tid & 7;
            const size_t xw = ((size_t)(bb*Sn + t))*Gn + bk*8 + jl;
            xg0 = g_XWenc[xw]; xg1 = g_XWenc[xw+1024];
            xg2 = g_XWenc[xw+2048]; xg3 = g_XWenc[xw+3072];
        }

        float acc[2][4][4];
        #pragma unroll
        for (int a = 0; a < 2; a++)
            #pragma unroll
            for (int b = 0; b < 4; b++)
                #pragma unroll
                for (int q = 0; q < 4; q++) acc[a][b][q] = 0.0f;

        const int cb = wid*4;
        #pragma unroll
        for (int kp = 0; kp < 2; kp++) {
            const int c0 = cb + kp*2;
            uint4 f00 = Af[(c0*2)*32 + lane],     f01 = Af[(c0*2+1)*32 + lane];
            uint4 f10 = Af[((c0+1)*2)*32 + lane], f11 = Af[((c0+1)*2+1)*32 + lane];
            #pragma unroll
            for (int nt = 0; nt < 4; nt++) {
                uint4 wq = w_hhE_f[((size_t)(nt*128 + bk)*32 + (c0>>1))*32 + lane];
                mma16816h(acc[0][nt], (u32*)&f00, wq.x, wq.y);
                mma16816h(acc[1][nt], (u32*)&f01, wq.x, wq.y);
                mma16816h(acc[0][nt], (u32*)&f10, wq.z, wq.w);
                mma16816h(acc[1][nt], (u32*)&f11, wq.z, wq.w);
            }
        }
        float* rw0 = &red_[wid*1056];
        #pragma unroll
        for (int mt = 0; mt < 2; mt++)
            #pragma unroll
            for (int nt = 0; nt < 4; nt++) {
                int r0 = mt*16 + g, c0 = nt*8 + tg*2;
                rw0[r0*33 + c0]       = acc[mt][nt][0];
                rw0[r0*33 + c0 + 1]   = acc[mt][nt][1];
                rw0[(r0+8)*33 + c0]   = acc[mt][nt][2];
                rw0[(r0+8)*33 + c0+1] = acc[mt][nt][3];
            }
        __syncthreads();

        if (tid < 256) {
            const int bb = tid >> 3, jl = tid & 7, j = bk*8 + jl;
            float gi = xg0, gf = xg1, gg = xg2, go = xg3;
            #pragma unroll
            for (int w = 0; w < 16; w++) {
                const float* rw = &red_[w*1056 + bb*33];
                gi += rw[jl]; gf += rw[8+jl]; gg += rw[16+jl]; go += rw[24+jl];
            }
            cst = sigm(gf)*cst + sigm(gi)*tanhf(gg);
            float h = sigm(go)*tanhf(cst);
            g_eo16[((size_t)(bb*Sn + t))*Hn + j] = fhi(h);
            frag_store16((u16*)g_ehf[wp2], bb, j, h);
            if (t == Sn-1) { g_h[bb*Hn + j] = h; g_c[bb*Hn + j] = cst; }
        }
        gbar();
    }
}

// ---------- persistent decoder: 3 phases/step ----------
__global__ void __launch_bounds__(512) dec_persist(const float* __restrict__ cls1_b)
{
    extern __shared__ float red_[];
    const int bk = blockIdx.x, tid = threadIdx.x, lane = tid & 31, wid = tid >> 5;
    const int g = lane >> 2, tg = lane & 3;
    float* sc    = red_;
    float* wsm   = sc + 3200;
    float* stats = wsm + 3200;
    float* ctx   = stats + 64;

    { int i = bk*512 + tid;
      if (i < Bn*Hn) {
          float h0 = g_h[i];
          int row = i >> 10, col = i & 1023;
          frag_store16((u16*)g_dhf[0], row, col, h0);
          frag_store16((u16*)g_fdf[0], row, col, h0);
      } }
    float cst = (tid < 256) ? g_c[(tid>>3)*Hn + bk*8 + (tid&7)] : 0.0f;
    gbar();

    for (int t = 0; t < Tn; t++) {
        const int rp = t & 1, wp2 = rp ^ 1;

        // ---- P1: gates + LSTM cell ----
        {
            const uint4 *Af, *Wf;
            int cb;
            if (wid < 8) { Af = g_fdf[rp]; Wf = w_ihDH_f; cb = wid*8; }
            else         { Af = g_dhf[rp]; Wf = w_hhD_f;  cb = (wid-8)*8; }

            float xg0, xg1, xg2, xg3;
            if (tid < 256) {
                const int bb = tid >> 3, jl = tid & 7;
                const size_t xw = ((size_t)(bb*Tn + t))*Gn + bk*8 + jl;
                xg0 = g_XWdec[xw]; xg1 = g_XWdec[xw+1024];
                xg2 = g_XWdec[xw+2048]; xg3 = g_XWdec[xw+3072];
            }

            float acc[2][4][4];
            #pragma unroll
            for (int a = 0; a < 2; a++)
                #pragma unroll
                for (int b = 0; b < 4; b++)
                    #pragma unroll
                    for (int q = 0; q < 4; q++) acc[a][b][q] = 0.0f;

            #pragma unroll
            for (int kp = 0; kp < 4; kp++) {
                const int c0 = cb + kp*2;
                uint4 f00 = Af[(c0*2)*32 + lane],     f01 = Af[(c0*2+1)*32 + lane];
                uint4 f10 = Af[((c0+1)*2)*32 + lane], f11 = Af[((c0+1)*2+1)*32 + lane];
                #pragma unroll
                for (int nt = 0; nt < 4; nt++) {
                    uint4 wq = Wf[((size_t)(nt*128 + bk)*32 + (c0>>1))*32 + lane];
                    mma16816h(acc[0][nt], (u32*)&f00, wq.x, wq.y);
                    mma16816h(acc[1][nt], (u32*)&f01, wq.x, wq.y);
                    mma16816h(acc[0][nt], (u32*)&f10, wq.z, wq.w);
                    mma16816h(acc[1][nt], (u32*)&f11, wq.z, wq.w);
                }
            }
            float* rw0 = &red_[wid*1056];
            #pragma unroll
            for (int mt = 0; mt < 2; mt++)
                #pragma unroll
                for (int nt = 0; nt < 4; nt++) {
                    int r0 = mt*16 + g, c0 = nt*8 + tg*2;
                    rw0[r0*33 + c0]       = acc[mt][nt][0];
                    rw0[r0*33 + c0 + 1]   = acc[mt][nt][1];
                    rw0[(r0+8)*33 + c0]   = acc[mt][nt][2];
                    rw0[(r0+8)*33 + c0+1] = acc[mt][nt][3];
                }
            __syncthreads();
            if (tid < 256) {
                const int bb = tid >> 3, jl = tid & 7, j = bk*8 + jl;
                float gi = xg0, gf = xg1, gg = xg2, go = xg3;
                #pragma unroll
                for (int w = 0; w < 16; w++) {
                    const float* rw = &red_[w*1056 + bb*33];
                    gi += rw[jl]; gf += rw[8+jl]; gg += rw[16+jl]; go += rw[24+jl];
                }
                cst = sigm(gf)*cst + sigm(gi)*tanhf(gg);
                float h = sigm(go)*tanhf(cst);
                g_hdf[bb*Hn + j] = h;
                frag_store16((u16*)g_dhf[wp2], bb, j, h);
            }
        }
        gbar();

        // ---- P2: h@W1b partial MMA + attention scores (fp16 proj) ----
        {
            const uint4* Af = g_dhf[wp2];
            const int cb = wid*4;
            float fa[2][4];
            #pragma unroll
            for (int a = 0; a < 2; a++)
                #pragma unroll
                for (int q = 0; q < 4; q++) fa[a][q] = 0.0f;
            #pragma unroll
            for (int kp = 0; kp < 2; kp++) {
                const int c0 = cb + kp*2;
                uint4 f00 = Af[(c0*2)*32 + lane],     f01 = Af[(c0*2+1)*32 + lane];
                uint4 f10 = Af[((c0+1)*2)*32 + lane], f11 = Af[((c0+1)*2+1)*32 + lane];
                uint4 wq = w_c1b_f[((size_t)bk*32 + (c0>>1))*32 + lane];
                mma16816h(fa[0], (u32*)&f00, wq.x, wq.y);
                mma16816h(fa[1], (u32*)&f01, wq.x, wq.y);
                mma16816h(fa[0], (u32*)&f10, wq.z, wq.w);
                mma16816h(fa[1], (u32*)&f11, wq.z, wq.w);
            }
            float* pb = red_ + PB_OFF + wid*256;
            #pragma unroll
            for (int mt = 0; mt < 2; mt++) {
                int r0 = mt*16 + g;
                pb[r0*8 + tg*2]       = fa[mt][0];
                pb[r0*8 + tg*2 + 1]   = fa[mt][1];
                pb[(r0+8)*8 + tg*2]   = fa[mt][2];
                pb[(r0+8)*8 + tg*2+1] = fa[mt][3];
            }
            #pragma unroll
            for (int r = 0; r < 2; r++) {
                int pair = bk*16 + wid + r*2048;
                if (pair < Bn*Sn) {
                    int b = pair / Sn;
                    const uint4* ep4 = (const uint4*)(g_pe16 + (size_t)pair * 2048);
                    const float4* hv4 = (const float4*)(g_hdf + b * Hn);
                    float a = 0.f;
                    #pragma unroll
                    for (int it = 0; it < 4; it++) {
                        uint4 e = ep4[lane + 32*it];
                        float4 h0 = hv4[(lane + 32*it)*2];
                        float4 h1 = hv4[(lane + 32*it)*2 + 1];
                        float2 e0 = __half22float2(*(__half2*)&e.x);
                        float2 e1 = __half22float2(*(__half2*)&e.y);
                        float2 e2 = __half22float2(*(__half2*)&e.z);
                        float2 e3 = __half22float2(*(__half2*)&e.w);
                        a += e0.x*h0.x + e0.y*h0.y + e1.x*h0.z + e1.y*h0.w
                           + e2.x*h1.x + e2.y*h1.y + e3.x*h1.z + e3.y*h1.w;
                    }
                    #pragma unroll
                    for (int o = 16; o; o >>= 1) a += __shfl_xor_sync(0xffffffffu, a, o);
                    if (lane == 0) g_scores[pair] = a;
                }
            }
        }
        gbar();

        // ---- P3: softmax + context-over-EP2 + feed ----
        for (int i = tid; i < Bn*Sn; i += 512) sc[i] = g_scores[i];
        __syncthreads();

        // prefetch EP2 operands (addresses independent of softmax)
        const int half3 = tid >> 8, ct3 = tid & 255;
        const int bb3 = ct3 >> 3, jl3 = ct3 & 7, j3 = bk*8 + jl3;
        u32 e2r[25];
        {
            const u16* e2 = g_pe16 + ((size_t)(bb3*Sn + half3*50))*2048 + 1024 + j3;
            #pragma unroll
            for (int s2 = 0; s2 < 25; s2++)
                e2r[s2] = pack2(e2[(size_t)(2*s2)*2048], e2[(size_t)(2*s2+1)*2048]);
        }

        #pragma unroll
        for (int q = 0; q < 2; q++) {
            int b = wid*2 + q;
            float m = -1e30f;
            for (int s = lane; s < Sn; s += 32) m = fmaxf(m, sc[b*Sn + s]);
            #pragma unroll
            for (int o = 16; o; o >>= 1) m = fmaxf(m, __shfl_xor_sync(0xffffffffu, m, o));
            float su = 0.f;
            for (int s = lane; s < Sn; s += 32) su += expf(sc[b*Sn + s] - m);
            #pragma unroll
            for (int o = 16; o; o >>= 1) su += __shfl_xor_sync(0xffffffffu, su, o);
            if (lane == 0) { stats[b] = m; stats[32 + b] = 1.0f / su; }
        }
        __syncthreads();
        for (int i = tid; i < Bn*Sn; i += 512) {
            int b = i / Sn;
            wsm[i] = expf(sc[i] - stats[b]) * stats[32 + b];
        }
        __syncthreads();
        {
            const float* wv = wsm + bb3*Sn + half3*50;
            float a = 0.f;
            #pragma unroll
            for (int s2 = 0; s2 < 25; s2++) {
                float2 e = __half22float2(*(__half2*)&e2r[s2]);
                a += wv[2*s2]*e.x + wv[2*s2+1]*e.y;
            }
            ctx[tid] = a;
        }
        __syncthreads();
        if (tid < 256) {
            const int bb = tid >> 3, jl = tid & 7, j = bk*8 + jl;
            float a = ctx[tid] + ctx[256 + tid] + cls1_b[j];
            #pragma unroll
            for (int w = 0; w < 16; w++) a += red_[PB_OFF + w*256 + bb*8 + jl];
            float f = tanhf(a);
            frag_store16((u16*)g_fdf[wp2], bb, j, f);
            g_hid16[((size_t)(bb*Tn + t))*Hn + j] = fhi(f);
        }
        gbar();
    }
}

extern "C" void kernel_launch(void* const* d_in, const int* in_sizes, int n_in,
                              void* d_out, int out_size)
{
    const int*   source_data = (const int*)  d_in[0];
    const int*   target_data = (const int*)  d_in[1];
    const float* src_emb  = (const float*)d_in[2];
    const float* tgt_emb  = (const float*)d_in[3];
    const float* enc_Wih  = (const float*)d_in[4];
    const float* enc_Whh  = (const float*)d_in[5];
    const float* enc_b    = (const float*)d_in[6];
    const float* dec_Wih  = (const float*)d_in[7];
    const float* dec_Whh  = (const float*)d_in[8];
    const float* dec_b    = (const float*)d_in[9];
    const float* att1_W   = (const float*)d_in[10];
    const float* att1_b   = (const float*)d_in[11];
    const float* cls1_W   = (const float*)d_in[12];
    const float* cls1_b   = (const float*)d_in[13];
    const float* cls2_W   = (const float*)d_in[14];
    const float* cls2_b   = (const float*)d_in[15];
    float* out = (float*)d_out;

    float *XWenc, *XWdec, *bias2;
    void *ihE_h,*ihE_l,*ihD0_h,*ihD0_l,*pe_h,*pe_l,*c2_h;
    void *hhE_f,*ihDH_f,*hhD_f,*c1b_f;
    void *hid16,*eo16,*pe16,*semb16,*temb16;
    cudaGetSymbolAddress((void**)&XWenc,  g_XWenc);
    cudaGetSymbolAddress((void**)&XWdec,  g_XWdec);
    cudaGetSymbolAddress((void**)&bias2,  g_bias2);
    cudaGetSymbolAddress(&hid16,  g_hid16);  cudaGetSymbolAddress(&eo16, g_eo16);
    cudaGetSymbolAddress(&pe16,   g_pe16);
    cudaGetSymbolAddress(&semb16, g_semb16); cudaGetSymbolAddress(&temb16, g_temb16);
    cudaGetSymbolAddress(&ihE_h,  w_ihE_h);  cudaGetSymbolAddress(&ihE_l,  w_ihE_l);
    cudaGetSymbolAddress(&ihD0_h, w_ihD0_h); cudaGetSymbolAddress(&ihD0_l, w_ihD0_l);
    cudaGetSymbolAddress(&pe_h,   w_pe_h);   cudaGetSymbolAddress(&pe_l,   w_pe_l);
    cudaGetSymbolAddress(&c2_h,   w_c2_h);
    cudaGetSymbolAddress(&hhE_f,  w_hhE_f);  cudaGetSymbolAddress(&ihDH_f, w_ihDH_f);
    cudaGetSymbolAddress(&hhD_f,  w_hhD_f);  cudaGetSymbolAddress(&c1b_f,  w_c1b_f);

    cudaFuncSetAttribute(enc_persist, cudaFuncAttributeMaxDynamicSharedMemorySize, RED_F*4);
    cudaFuncSetAttribute(dec_persist, cudaFuncAttributeMaxDynamicSharedMemorySize, RED_F*4);

    CJobs jb;
    jb.j[0]  = { enc_Wih,                     ihE_h,  ihE_l,   512, 4096, 3, 0     };
    jb.j[1]  = { dec_Wih,                     ihD0_h, ihD0_l,  512, 4096, 3, 2048  };
    jb.j[2]  = { att1_W,                      pe_h,   pe_l,   1024, 1024, 3, 4096  };
    jb.j[3]  = { cls2_W,                      c2_h,   nullptr,1024, Vn,   4, 5120  };
    jb.j[4]  = { cls1_W,  (u16*)pe_h + (size_t)1024*1024,
                          (u16*)pe_l + (size_t)1024*1024,     1024, 1024, 3, 37120 };
    jb.j[5]  = { enc_Whh,                     hhE_f,  nullptr,1024, 4096, 1, 38144 };
    jb.j[6]  = { dec_Wih + (size_t)512*4096,  ihDH_f, nullptr,1024, 4096, 1, 40192 };
    jb.j[7]  = { dec_Whh,                     hhD_f,  nullptr,1024, 4096, 1, 42240 };
    jb.j[8]  = { cls1_W + (size_t)1024*1024,  c1b_f,  nullptr,1024, 1024, 1, 44288 };
    jb.j[9]  = { src_emb, semb16, (void*)source_data,  512, 0, 5, 44800 };
    jb.j[10] = { tgt_emb, temb16, (void*)target_data,  512, 0, 5, 48000 };
    jb.j[11] = { att1_b,  bias2,  nullptr,            1024, 0, 6, 51200 };
    conv_all<<<51201, 256>>>(jb);                                              // 1

    gemm_h16<<<dim3(25, 32), 256>>>((u16*)semb16,
        (u16*)ihE_h, (u16*)ihE_l, enc_b, XWenc, nullptr, Gn, En);              // 2
    gemm_h16<<<dim3(25, 32), 256>>>((u16*)temb16,
        (u16*)ihD0_h, (u16*)ihD0_l, dec_b, XWdec, nullptr, Gn, En);            // 3
    enc_persist<<<NBLK, 512, RED_F*4>>>();                                     // 4
    gemm_h16<<<dim3(25, 16), 256>>>((u16*)eo16,
        (u16*)pe_h, (u16*)pe_l, bias2, nullptr, (u16*)pe16, 2048, Hn);         // 5
    dec_persist<<<NBLK, 512, RED_F*4>>>(cls1_b);                               // 6
    gemm_h16s<<<dim3(25, 250), 256>>>((u16*)hid16,
        (u16*)c2_h, cls2_b, out, Vn, Hn);                                      // 7
}